// round 10
// baseline (speedup 1.0000x reference)
#include <cuda_runtime.h>
#include <cstdint>

// LocalAttention fused kernel v5 (sm_103a).
// T[b,l,j] = dot(x[b,l,:], W[j,:]) for 18 rows (aw3:0-2, aw5:3-7, aw7:8-14, cw:15-17)
// out_k[b,l] = tanh( sigmoid(shifted-sum of T + ab_k) * T[.,dcol_k] + cb_k )
//
// v5 = v2 (74.2us best) + minimal changes:
//  - NBUF=3 ring, ONE __syncthreads per chunk (v2 had 2)
//  - CH=3: 75 = 25x3 exactly -> 25 chunks/syncs (v2: 38 sync events), no tail
//    masking, weight pitch 300 (no pad); 57.3KB smem -> still 4 blocks/SM
//  - stage(c+2) issued right after the sync, BEFORE compute(c): 2-chunk-deep
//    DMA pipeline with a full compute-chunk of latency slack
//  - grid (3 x 256) = 768 blocks for finer load balance

typedef unsigned long long ull;

#define FMA2(d, a, b) \
    asm("fma.rn.f32x2 %0, %1, %2, %0;" : "+l"(d) : "l"(a), "l"(b))

__device__ __forceinline__ float unpk_sum(ull v) {
    float lo, hi;
    asm("mov.b64 {%0, %1}, %2;" : "=f"(lo), "=f"(hi) : "l"(v));
    return lo + hi;
}

__device__ __forceinline__ float sigm(float v) {
    return 1.0f / (1.0f + __expf(-v));
}

constexpr int Lc = 500;
constexpr int Ec = 300;
constexpr int E4 = 75;             // float4 per x row
constexpr int CH = 3;              // float4 per row per chunk
constexpr int NCHUNK = 25;         // 75 / 3, exact
constexpr int POS = 248;           // rows staged per block
constexpr int TL  = 242;           // outputs per block (pos 3..244)
constexpr int NJ  = 18;
constexpr int WPITCH = 300;        // weight row pitch, words (no pad needed)
constexpr int XROW_W = 12;         // words per row per chunk buffer (3 float4)
constexpr int XBUF_W = POS * XROW_W;               // 2976 words = 11904 B
constexpr int NBUF = 3;
constexpr int WS_OFF = NBUF * XBUF_W;              // 8928 words
constexpr int SMEM_WORDS = WS_OFF + NJ * WPITCH;   // 14328
constexpr int SMEM_BYTES = SMEM_WORDS * 4;         // 57312 B -> 4 blocks/SM
constexpr int NITEM = POS * CH;                    // 744 16B items per chunk

__global__ __launch_bounds__(128, 4)
void la_fused5(const float* __restrict__ x,
               const float* __restrict__ aw3, const float* __restrict__ ab3,
               const float* __restrict__ cw3, const float* __restrict__ cb3,
               const float* __restrict__ aw5, const float* __restrict__ ab5,
               const float* __restrict__ cw5, const float* __restrict__ cb5,
               const float* __restrict__ aw7, const float* __restrict__ ab7,
               const float* __restrict__ cw7, const float* __restrict__ cb7,
               float* __restrict__ out, int Ltot)
{
    extern __shared__ float sm[];
    float* ws = sm + WS_OFF;

    const int tid  = threadIdx.x;
    const int b    = blockIdx.y;
    const int tile = blockIdx.x;
    const int l_base = tile * TL - 3;
    const float* xrow0 = x + (size_t)b * Lc * Ec;

    uint32_t sbase;
    asm("{ .reg .u64 t; cvta.to.shared.u64 t, %1; cvt.u32.u64 %0, t; }"
        : "=r"(sbase) : "l"(sm));
    const uint32_t bufB[3] = { sbase, sbase + XBUF_W * 4, sbase + 2 * XBUF_W * 4 };

    // ---- staging state: 6 16B items per thread per chunk ----
    // item f = tid + 128*i maps to (cl = f/248, r = f%248); advances +12 floats/chunk
    const float* gsrc[6];
    uint32_t     soff[6];
    int          gsz[6];
    #pragma unroll
    for (int i = 0; i < 6; ++i) {
        int f  = tid + 128 * i;
        int cl = (f >= 2 * POS) ? 2 : ((f >= POS) ? 1 : 0);
        int r  = f - cl * POS;
        int l  = l_base + r;
        bool ok = (f < NITEM) && (l >= 0) && (l < Lc);
        gsrc[i] = xrow0 + (ok ? (size_t)l * Ec : 0) + cl * 4;
        soff[i] = (uint32_t)((r * XROW_W + cl * 4) * 4);
        gsz[i]  = ok ? 16 : 0;
    }

    // stage chunk c into the given buffer; always commits exactly one group
    auto stage = [&](int c, uint32_t base) {
        if (c < NCHUNK) {
            #pragma unroll
            for (int i = 0; i < 6; ++i) {
                if (i < 5 || tid < NITEM - 5 * 128) {   // i=5 only for tid<104
                    asm volatile("cp.async.cg.shared.global [%0], [%1], 16, %2;"
                                 :: "r"(base + soff[i]), "l"(gsrc[i]), "r"(gsz[i]));
                }
                gsrc[i] += CH * 4;      // next chunk: +48 B
            }
        }
        asm volatile("cp.async.commit_group;");
    };

    // ---- kick off DMA first ----
    stage(0, bufB[0]);
    stage(1, bufB[1]);

    // ---- weights -> shared (contiguous, pitch 300) ----
    for (int i = tid; i < 3 * Ec; i += 128) ws[i]           = aw3[i];
    for (int i = tid; i < 5 * Ec; i += 128) ws[3 * Ec + i]  = aw5[i];
    for (int i = tid; i < 7 * Ec; i += 128) ws[8 * Ec + i]  = aw7[i];
    for (int i = tid; i < Ec; i += 128) {
        ws[15 * Ec + i] = cw3[i];
        ws[16 * Ec + i] = cw5[i];
        ws[17 * Ec + i] = cw7[i];
    }

    const int posA = tid;            // rows 0..127
    const int posB = tid + 120;      // rows 120..247 (8 rows redundantly computed)

    ull accA[NJ], accB[NJ];
    #pragma unroll
    for (int j = 0; j < NJ; ++j) { accA[j] = 0ull; accB[j] = 0ull; }

    int cbuf = 0, nbuf = 2;
    for (int c = 0; c < NCHUNK; ++c) {
        asm volatile("cp.async.wait_group 1;" ::: "memory");  // chunk c landed
        __syncthreads();      // everyone's chunk-c DMA done + compute(c-1) done
        stage(c + 2, bufB[nbuf]);                             // overwrite-safe

        const float* xb = sm + cbuf * XBUF_W;
        const float* pA = xb + posA * XROW_W;
        const float* pB = xb + posB * XROW_W;
        const float* wc = ws + c * (CH * 4);

        #pragma unroll
        for (int e = 0; e < CH; ++e) {
            ulonglong2 xa = *(const ulonglong2*)(pA + e * 4);
            ulonglong2 xv = *(const ulonglong2*)(pB + e * 4);
            #pragma unroll
            for (int j = 0; j < NJ; ++j) {
                ulonglong2 wv = *(const ulonglong2*)(wc + j * WPITCH + e * 4);
                FMA2(accA[j], xa.x, wv.x);
                FMA2(accA[j], xa.y, wv.y);
                FMA2(accB[j], xv.x, wv.x);
                FMA2(accB[j], xv.y, wv.y);
            }
        }
        cbuf = (cbuf == 2) ? 0 : cbuf + 1;
        nbuf = (nbuf == 2) ? 0 : nbuf + 1;
    }

    // ---- T aliases the (dead) x buffers: 248 rows x 19 words ----
    __syncthreads();
    float* Tsh = sm;
    #pragma unroll
    for (int j = 0; j < NJ; ++j) {
        Tsh[posA * 19 + j] = unpk_sum(accA[j]);
        Tsh[posB * 19 + j] = unpk_sum(accB[j]);   // rows 120-127: same-value race, benign
    }
    __syncthreads();

    // ---- epilogue: shifted sums + sigmoid gate + tanh ----
    const float sab3 = ab3[0], scb3 = cb3[0];
    const float sab5 = ab5[0], scb5 = cb5[0];
    const float sab7 = ab7[0], scb7 = cb7[0];

    #pragma unroll
    for (int half = 0; half < 2; ++half) {
        const int pos = tid + half * 128;
        const int l_out = l_base + pos;
        if (pos >= 3 && pos <= POS - 4 && l_out < Lc) {
            const float* T0 = &Tsh[pos * 19];
            float s3 = Tsh[(pos - 1) * 19 + 0] + T0[1] + Tsh[(pos + 1) * 19 + 2];
            float s5 = 0.f;
            #pragma unroll
            for (int j = 0; j < 5; ++j) s5 += Tsh[(pos - 2 + j) * 19 + 3 + j];
            float s7 = 0.f;
            #pragma unroll
            for (int j = 0; j < 7; ++j) s7 += Tsh[(pos - 3 + j) * 19 + 8 + j];

            float o3 = tanhf(sigm(s3 + sab3) * T0[15] + scb3);
            float o5 = tanhf(sigm(s5 + sab5) * T0[16] + scb5);
            float o7 = tanhf(sigm(s7 + sab7) * T0[17] + scb7);

            const size_t oi = (size_t)b * Lc + l_out;
            out[oi]                    = o3;
            out[(size_t)Ltot + oi]     = o5;
            out[2 * (size_t)Ltot + oi] = o7;
        }
    }
}

extern "C" void kernel_launch(void* const* d_in, const int* in_sizes, int n_in,
                              void* d_out, int out_size) {
    const float* x   = (const float*)d_in[0];
    const float* aw3 = (const float*)d_in[1];
    const float* ab3 = (const float*)d_in[2];
    const float* cw3 = (const float*)d_in[3];
    const float* cb3 = (const float*)d_in[4];
    const float* aw5 = (const float*)d_in[5];
    const float* ab5 = (const float*)d_in[6];
    const float* cw5 = (const float*)d_in[7];
    const float* cb5 = (const float*)d_in[8];
    const float* aw7 = (const float*)d_in[9];
    const float* ab7 = (const float*)d_in[10];
    const float* cw7 = (const float*)d_in[11];
    const float* cb7 = (const float*)d_in[12];
    float* out = (float*)d_out;

    const int Bn   = in_sizes[0] / (Lc * Ec);   // 256
    const int Ltot = Bn * Lc;

    cudaFuncSetAttribute(la_fused5, cudaFuncAttributeMaxDynamicSharedMemorySize,
                         SMEM_BYTES);

    dim3 grid(3, Bn);    // 3 l-tiles x 256 batches = 768 blocks
    dim3 block(128);
    la_fused5<<<grid, block, SMEM_BYTES>>>(x,
                                           aw3, ab3, cw3, cb3,
                                           aw5, ab5, cw5, cb5,
                                           aw7, ab7, cw7, cb7,
                                           out, Ltot);
}

// round 12
// speedup vs baseline: 1.0625x; 1.0625x over previous
#include <cuda_runtime.h>
#include <cstdint>

// LocalAttention fused kernel v5 (sm_103a).
// T[b,l,j] = dot(x[b,l,:], W[j,:]) for 18 rows (aw3:0-2, aw5:3-7, aw7:8-14, cw:15-17)
// out_k[b,l] = tanh( sigmoid(shifted-sum of T + ab_k) * T[.,dcol_k] + cb_k )
//
// v5 = v2 (74.2us best) + minimal changes:
//  - NBUF=3 ring, ONE __syncthreads per chunk (v2 had 2)
//  - CH=3: 75 = 25x3 exactly -> 25 chunks/syncs (v2: 38 sync events), no tail
//    masking, weight pitch 300 (no pad); 57.3KB smem -> still 4 blocks/SM
//  - stage(c+2) issued right after the sync, BEFORE compute(c): 2-chunk-deep
//    DMA pipeline with a full compute-chunk of latency slack
//  - grid (3 x 256) = 768 blocks for finer load balance

typedef unsigned long long ull;

#define FMA2(d, a, b) \
    asm("fma.rn.f32x2 %0, %1, %2, %0;" : "+l"(d) : "l"(a), "l"(b))

__device__ __forceinline__ float unpk_sum(ull v) {
    float lo, hi;
    asm("mov.b64 {%0, %1}, %2;" : "=f"(lo), "=f"(hi) : "l"(v));
    return lo + hi;
}

__device__ __forceinline__ float sigm(float v) {
    return 1.0f / (1.0f + __expf(-v));
}

constexpr int Lc = 500;
constexpr int Ec = 300;
constexpr int E4 = 75;             // float4 per x row
constexpr int CH = 3;              // float4 per row per chunk
constexpr int NCHUNK = 25;         // 75 / 3, exact
constexpr int POS = 248;           // rows staged per block
constexpr int TL  = 242;           // outputs per block (pos 3..244)
constexpr int NJ  = 18;
constexpr int WPITCH = 300;        // weight row pitch, words (no pad needed)
constexpr int XROW_W = 12;         // words per row per chunk buffer (3 float4)
constexpr int XBUF_W = POS * XROW_W;               // 2976 words = 11904 B
constexpr int NBUF = 3;
constexpr int WS_OFF = NBUF * XBUF_W;              // 8928 words
constexpr int SMEM_WORDS = WS_OFF + NJ * WPITCH;   // 14328
constexpr int SMEM_BYTES = SMEM_WORDS * 4;         // 57312 B -> 4 blocks/SM
constexpr int NITEM = POS * CH;                    // 744 16B items per chunk

__global__ __launch_bounds__(128, 4)
void la_fused5(const float* __restrict__ x,
               const float* __restrict__ aw3, const float* __restrict__ ab3,
               const float* __restrict__ cw3, const float* __restrict__ cb3,
               const float* __restrict__ aw5, const float* __restrict__ ab5,
               const float* __restrict__ cw5, const float* __restrict__ cb5,
               const float* __restrict__ aw7, const float* __restrict__ ab7,
               const float* __restrict__ cw7, const float* __restrict__ cb7,
               float* __restrict__ out, int Ltot)
{
    extern __shared__ float sm[];
    float* ws = sm + WS_OFF;

    const int tid  = threadIdx.x;
    const int b    = blockIdx.y;
    const int tile = blockIdx.x;
    const int l_base = tile * TL - 3;
    const float* xrow0 = x + (size_t)b * Lc * Ec;

    uint32_t sbase;
    asm("{ .reg .u64 t; cvta.to.shared.u64 t, %1; cvt.u32.u64 %0, t; }"
        : "=r"(sbase) : "l"(sm));
    const uint32_t bufB[3] = { sbase, sbase + XBUF_W * 4, sbase + 2 * XBUF_W * 4 };

    // ---- staging state: 6 16B items per thread per chunk ----
    // item f = tid + 128*i maps to (cl = f/248, r = f%248); advances +12 floats/chunk
    const float* gsrc[6];
    uint32_t     soff[6];
    int          gsz[6];
    #pragma unroll
    for (int i = 0; i < 6; ++i) {
        int f  = tid + 128 * i;
        int cl = (f >= 2 * POS) ? 2 : ((f >= POS) ? 1 : 0);
        int r  = f - cl * POS;
        int l  = l_base + r;
        bool ok = (f < NITEM) && (l >= 0) && (l < Lc);
        gsrc[i] = xrow0 + (ok ? (size_t)l * Ec : 0) + cl * 4;
        soff[i] = (uint32_t)((r * XROW_W + cl * 4) * 4);
        gsz[i]  = ok ? 16 : 0;
    }

    // stage chunk c into the given buffer; always commits exactly one group
    auto stage = [&](int c, uint32_t base) {
        if (c < NCHUNK) {
            #pragma unroll
            for (int i = 0; i < 6; ++i) {
                if (i < 5 || tid < NITEM - 5 * 128) {   // i=5 only for tid<104
                    asm volatile("cp.async.cg.shared.global [%0], [%1], 16, %2;"
                                 :: "r"(base + soff[i]), "l"(gsrc[i]), "r"(gsz[i]));
                }
                gsrc[i] += CH * 4;      // next chunk: +48 B
            }
        }
        asm volatile("cp.async.commit_group;");
    };

    // ---- kick off DMA first ----
    stage(0, bufB[0]);
    stage(1, bufB[1]);

    // ---- weights -> shared (contiguous, pitch 300) ----
    for (int i = tid; i < 3 * Ec; i += 128) ws[i]           = aw3[i];
    for (int i = tid; i < 5 * Ec; i += 128) ws[3 * Ec + i]  = aw5[i];
    for (int i = tid; i < 7 * Ec; i += 128) ws[8 * Ec + i]  = aw7[i];
    for (int i = tid; i < Ec; i += 128) {
        ws[15 * Ec + i] = cw3[i];
        ws[16 * Ec + i] = cw5[i];
        ws[17 * Ec + i] = cw7[i];
    }

    const int posA = tid;            // rows 0..127
    const int posB = tid + 120;      // rows 120..247 (8 rows redundantly computed)

    ull accA[NJ], accB[NJ];
    #pragma unroll
    for (int j = 0; j < NJ; ++j) { accA[j] = 0ull; accB[j] = 0ull; }

    int cbuf = 0, nbuf = 2;
    for (int c = 0; c < NCHUNK; ++c) {
        asm volatile("cp.async.wait_group 1;" ::: "memory");  // chunk c landed
        __syncthreads();      // everyone's chunk-c DMA done + compute(c-1) done
        stage(c + 2, bufB[nbuf]);                             // overwrite-safe

        const float* xb = sm + cbuf * XBUF_W;
        const float* pA = xb + posA * XROW_W;
        const float* pB = xb + posB * XROW_W;
        const float* wc = ws + c * (CH * 4);

        #pragma unroll
        for (int e = 0; e < CH; ++e) {
            ulonglong2 xa = *(const ulonglong2*)(pA + e * 4);
            ulonglong2 xv = *(const ulonglong2*)(pB + e * 4);
            #pragma unroll
            for (int j = 0; j < NJ; ++j) {
                ulonglong2 wv = *(const ulonglong2*)(wc + j * WPITCH + e * 4);
                FMA2(accA[j], xa.x, wv.x);
                FMA2(accA[j], xa.y, wv.y);
                FMA2(accB[j], xv.x, wv.x);
                FMA2(accB[j], xv.y, wv.y);
            }
        }
        cbuf = (cbuf == 2) ? 0 : cbuf + 1;
        nbuf = (nbuf == 2) ? 0 : nbuf + 1;
    }

    // ---- T aliases the (dead) x buffers: 248 rows x 19 words ----
    __syncthreads();
    float* Tsh = sm;
    #pragma unroll
    for (int j = 0; j < NJ; ++j) {
        Tsh[posA * 19 + j] = unpk_sum(accA[j]);
        Tsh[posB * 19 + j] = unpk_sum(accB[j]);   // rows 120-127: same-value race, benign
    }
    __syncthreads();

    // ---- epilogue: shifted sums + sigmoid gate + tanh ----
    const float sab3 = ab3[0], scb3 = cb3[0];
    const float sab5 = ab5[0], scb5 = cb5[0];
    const float sab7 = ab7[0], scb7 = cb7[0];

    #pragma unroll
    for (int half = 0; half < 2; ++half) {
        const int pos = tid + half * 128;
        const int l_out = l_base + pos;
        if (pos >= 3 && pos <= POS - 4 && l_out < Lc) {
            const float* T0 = &Tsh[pos * 19];
            float s3 = Tsh[(pos - 1) * 19 + 0] + T0[1] + Tsh[(pos + 1) * 19 + 2];
            float s5 = 0.f;
            #pragma unroll
            for (int j = 0; j < 5; ++j) s5 += Tsh[(pos - 2 + j) * 19 + 3 + j];
            float s7 = 0.f;
            #pragma unroll
            for (int j = 0; j < 7; ++j) s7 += Tsh[(pos - 3 + j) * 19 + 8 + j];

            float o3 = tanhf(sigm(s3 + sab3) * T0[15] + scb3);
            float o5 = tanhf(sigm(s5 + sab5) * T0[16] + scb5);
            float o7 = tanhf(sigm(s7 + sab7) * T0[17] + scb7);

            const size_t oi = (size_t)b * Lc + l_out;
            out[oi]                    = o3;
            out[(size_t)Ltot + oi]     = o5;
            out[2 * (size_t)Ltot + oi] = o7;
        }
    }
}

extern "C" void kernel_launch(void* const* d_in, const int* in_sizes, int n_in,
                              void* d_out, int out_size) {
    const float* x   = (const float*)d_in[0];
    const float* aw3 = (const float*)d_in[1];
    const float* ab3 = (const float*)d_in[2];
    const float* cw3 = (const float*)d_in[3];
    const float* cb3 = (const float*)d_in[4];
    const float* aw5 = (const float*)d_in[5];
    const float* ab5 = (const float*)d_in[6];
    const float* cw5 = (const float*)d_in[7];
    const float* cb5 = (const float*)d_in[8];
    const float* aw7 = (const float*)d_in[9];
    const float* ab7 = (const float*)d_in[10];
    const float* cw7 = (const float*)d_in[11];
    const float* cb7 = (const float*)d_in[12];
    float* out = (float*)d_out;

    const int Bn   = in_sizes[0] / (Lc * Ec);   // 256
    const int Ltot = Bn * Lc;

    cudaFuncSetAttribute(la_fused5, cudaFuncAttributeMaxDynamicSharedMemorySize,
                         SMEM_BYTES);

    dim3 grid(3, Bn);    // 3 l-tiles x 256 batches = 768 blocks
    dim3 block(128);
    la_fused5<<<grid, block, SMEM_BYTES>>>(x,
                                           aw3, ab3, cw3, cb3,
                                           aw5, ab5, cw5, cb5,
                                           aw7, ab7, cw7, cb7,
                                           out, Ltot);
}